// round 15
// baseline (speedup 1.0000x reference)
#include <cuda_runtime.h>
#include <stdint.h>
#include <math.h>

// ============================================================================
// Actor_att1 — R14: full tensor-core entity encoders.
// Layer1 (K<=5 -> 32) AND layer2 (32 -> 16) both via mma.sync.m16n8k8 tf32.
// The layer1 C-fragment feeds layer2's A-fragment directly via a permuted
// hidden-dim labeling (k-slot 8s+u <-> hidden 8s+2u / 8s+2(u-4)+1), encoded
// purely in how W2 rows are indexed when building B-fragments. Zero cross-
// lane exchange in the hot loop. Warp = 32 rows; lane: q=l/4, t=l%4.
// Items: 16T + q + 8b  (b = mma row-half). Softmax/LN fp32 + quad shfl.
// Merge head via mma with smem round-trip (as R13).
// ============================================================================

typedef unsigned long long u64;
#define DINL __device__ __forceinline__

DINL u64 f2pack(float lo, float hi){u64 d;asm("mov.b64 %0,{%1,%2};":"=l"(d):"f"(lo),"f"(hi));return d;}
DINL u64 f2splat(float v){u64 d;asm("mov.b64 %0,{%1,%1};":"=l"(d):"f"(v));return d;}
DINL void f2unpack(u64 v,float&lo,float&hi){asm("mov.b64 {%0,%1},%2;":"=f"(lo),"=f"(hi):"l"(v));}
DINL u64 f2fma(u64 a,u64 b,u64 c){u64 d;asm("fma.rn.f32x2 %0,%1,%2,%3;":"=l"(d):"l"(a),"l"(b),"l"(c));return d;}
DINL u64 f2mul(u64 a,u64 b){u64 d;asm("mul.rn.f32x2 %0,%1,%2;":"=l"(d):"l"(a),"l"(b));return d;}
DINL u64 f2add(u64 a,u64 b){u64 d;asm("add.rn.f32x2 %0,%1,%2;":"=l"(d):"l"(a),"l"(b));return d;}
DINL u64 sh1(u64 v){return __shfl_xor_sync(0xffffffffu,v,1);}
DINL u64 sh2(u64 v){return __shfl_xor_sync(0xffffffffu,v,2);}
DINL float sf1(float v){return __shfl_xor_sync(0xffffffffu,v,1);}
DINL float sf2(float v){return __shfl_xor_sync(0xffffffffu,v,2);}

// weights: round-to-nearest tf32 (cold path)
DINL uint32_t tf32w(float x){uint32_t u;asm("cvt.rna.tf32.f32 %0,%1;":"=r"(u):"f"(x));return u;}
// activations: raw fp32 bits (HW truncates; hot path, free)
DINL uint32_t tf32a(float x){return __float_as_uint(x);}

DINL void mma8(float&c0,float&c1,float&c2,float&c3,
               uint32_t a0,uint32_t a1,uint32_t a2,uint32_t a3,
               uint32_t b0,uint32_t b1){
    asm("mma.sync.aligned.m16n8k8.row.col.f32.tf32.tf32.f32 "
        "{%0,%1,%2,%3},{%4,%5,%6,%7},{%8,%9},{%0,%1,%2,%3};"
        : "+f"(c0),"+f"(c1),"+f"(c2),"+f"(c3)
        : "r"(a0),"r"(a1),"r"(a2),"r"(a3),"r"(b0),"r"(b1));
}

DINL float lrelu(float x){ return fmaxf(x, 0.01f * x); }

#define NT 384
#define ROWS 384
#define OBS 127

struct SW {
    float en_w1[4 * 32];  float en_b1[32];  float en_w2[32 * 16]; float en_b2[16];
    float oa_w1[5 * 32];  float oa_b1[32];  float oa_w2[32 * 16]; float oa_b2[16];
    float oa_g[16];       float oa_bln[16];
    float g_w1[3 * 32];   float g_b1[32];   float g_w2[32 * 16];  float g_b2[16];
    float g_g[16];        float g_bln[16];
    float m_w1[48 * 32];  float m_b1[32];   float m_w2[32 * 32];  float m_b2[32];
    float m_w3[32 * 2];   float m_b3[16];
};

DINL void cp_smem(float* dst, const float* __restrict__ src, int n, int tid) {
    for (int i = tid; i < n; i += NT) dst[i] = src[i];
}

// Per-encoder register-resident fragments.
struct EncW {
    uint32_t B1[4][2];   // layer1 B-fragments (k=t / k=t+4, col=8s+q)
    u64      b1p[4];     // layer1 bias pairs (cols 8s+2t, 8s+2t+1)
    uint32_t Bf[2][4][2];// layer2 B-fragments, permuted hidden rows
    float    b2v[2][2];  // layer2 bias (cols 8N+2t, +1)
};

template<int K>
DINL void load_encw(EncW& E, const float* __restrict__ w1,
                    const float* __restrict__ b1,
                    const float* __restrict__ w2,
                    const float* __restrict__ b2, int q, int t) {
#pragma unroll
    for (int s = 0; s < 4; s++) {
        E.B1[s][0] = (t < K)     ? tf32w(w1[t * 32 + 8 * s + q])       : 0u;
        E.B1[s][1] = (t + 4 < K) ? tf32w(w1[(t + 4) * 32 + 8 * s + q]) : 0u;
        E.b1p[s] = f2pack(b1[8 * s + 2 * t], b1[8 * s + 2 * t + 1]);
    }
#pragma unroll
    for (int N = 0; N < 2; N++) {
#pragma unroll
        for (int s = 0; s < 4; s++) {
            E.Bf[N][s][0] = tf32w(w2[(8 * s + 2 * t) * 16 + 8 * N + q]);
            E.Bf[N][s][1] = tf32w(w2[(8 * s + 2 * t + 1) * 16 + 8 * N + q]);
        }
        E.b2v[N][0] = b2[8 * N + 2 * t];
        E.b2v[N][1] = b2[8 * N + 2 * t + 1];
    }
}

// Entity encoder for one T-block: layer1 mma (4 n-tiles) -> relu -> layer2
// mma (2 n-tiles, 4 k-steps). Output: epT[N][b] relu'd pairs (cols 8N+2t,
// 8N+2t+1) for items row q (b=0) and q+8 (b=1).
DINL void enc_mma(uint32_t a0, uint32_t a1, uint32_t a2, uint32_t a3,
                  const EncW& E, u64 (&epT)[2][2]) {
    float h[4][4];
#pragma unroll
    for (int s = 0; s < 4; s++) {
        float blo, bhi; f2unpack(E.b1p[s], blo, bhi);
        float c0 = blo, c1 = bhi, c2 = blo, c3 = bhi;
        mma8(c0, c1, c2, c3, a0, a1, a2, a3, E.B1[s][0], E.B1[s][1]);
        h[s][0] = fmaxf(c0, 0.f);   // H[q][8s+2t]
        h[s][1] = fmaxf(c1, 0.f);   // H[q][8s+2t+1]
        h[s][2] = fmaxf(c2, 0.f);   // H[q+8][8s+2t]
        h[s][3] = fmaxf(c3, 0.f);   // H[q+8][8s+2t+1]
    }
#pragma unroll
    for (int N = 0; N < 2; N++) {
        float c0 = E.b2v[N][0], c1 = E.b2v[N][1];
        float c2 = E.b2v[N][0], c3 = E.b2v[N][1];
#pragma unroll
        for (int s = 0; s < 4; s++)
            mma8(c0, c1, c2, c3,
                 tf32a(h[s][0]), tf32a(h[s][2]), tf32a(h[s][1]), tf32a(h[s][3]),
                 E.Bf[N][s][0], E.Bf[N][s][1]);
        epT[N][0] = f2pack(fmaxf(c0, 0.f), fmaxf(c1, 0.f));
        epT[N][1] = f2pack(fmaxf(c2, 0.f), fmaxf(c3, 0.f));
    }
}

__global__ void __launch_bounds__(NT, 1)
actor_kernel(const float* __restrict__ s_in,
             const float* __restrict__ en_w1, const float* __restrict__ en_b1,
             const float* __restrict__ en_w2, const float* __restrict__ en_b2,
             const float* __restrict__ oa_w1, const float* __restrict__ oa_b1,
             const float* __restrict__ oa_w2, const float* __restrict__ oa_b2,
             const float* __restrict__ oa_g,  const float* __restrict__ oa_bln,
             const float* __restrict__ g_w1,  const float* __restrict__ g_b1,
             const float* __restrict__ g_w2,  const float* __restrict__ g_b2,
             const float* __restrict__ g_g,   const float* __restrict__ g_bln,
             const float* __restrict__ m_w1,  const float* __restrict__ m_b1,
             const float* __restrict__ m_w2,  const float* __restrict__ m_b2,
             const float* __restrict__ m_w3,  const float* __restrict__ m_b3,
             float* __restrict__ out, int B)
{
    extern __shared__ __align__(16) float smem[];
    float* xs = smem;                              // ROWS*OBS floats
    SW* sw = reinterpret_cast<SW*>(xs + ROWS * OBS);

    const int tid = threadIdx.x;

    // ---- coalesced input staging (tail zero-filled) ----
    {
        const size_t base = (size_t)blockIdx.x * ROWS * OBS;
        const size_t tot = (size_t)B * OBS;
        const float4* src4 = reinterpret_cast<const float4*>(s_in + base);
        float4* dst4 = reinterpret_cast<float4*>(xs);
        const int full4 = ROWS * OBS / 4;
        int n4 = full4;
        if (base + (size_t)full4 * 4 > tot) n4 = (int)((tot - base) / 4);
        for (int i = tid; i < n4; i += NT) dst4[i] = src4[i];
        if (n4 < full4) {
            float4 z = make_float4(0.f, 0.f, 0.f, 0.f);
            for (int i = n4 + tid; i < full4; i += NT) dst4[i] = z;
        }
    }

    cp_smem(sw->en_w1, en_w1, 4 * 32, tid);
    cp_smem(sw->en_b1, en_b1, 32, tid);
    cp_smem(sw->en_w2, en_w2, 32 * 16, tid);
    cp_smem(sw->en_b2, en_b2, 16, tid);
    cp_smem(sw->oa_w1, oa_w1, 5 * 32, tid);
    cp_smem(sw->oa_b1, oa_b1, 32, tid);
    cp_smem(sw->oa_w2, oa_w2, 32 * 16, tid);
    cp_smem(sw->oa_b2, oa_b2, 16, tid);
    cp_smem(sw->oa_g, oa_g, 16, tid);
    cp_smem(sw->oa_bln, oa_bln, 16, tid);
    cp_smem(sw->g_w1, g_w1, 3 * 32, tid);
    cp_smem(sw->g_b1, g_b1, 32, tid);
    cp_smem(sw->g_w2, g_w2, 32 * 16, tid);
    cp_smem(sw->g_b2, g_b2, 16, tid);
    cp_smem(sw->g_g, g_g, 16, tid);
    cp_smem(sw->g_bln, g_bln, 16, tid);
    cp_smem(sw->m_w1, m_w1, 48 * 32, tid);
    cp_smem(sw->m_b1, m_b1, 32, tid);
    cp_smem(sw->m_w2, m_w2, 32 * 32, tid);
    cp_smem(sw->m_b2, m_b2, 32, tid);
    cp_smem(sw->m_w3, m_w3, 32 * 2, tid);
    if (tid < 2) sw->m_b3[tid] = m_b3[tid];
    __syncthreads();

    const int warp = tid >> 5;
    const int lane = tid & 31;
    const int q = lane >> 2;          // mma row group 0..7
    const int t = lane & 3;           // role 0..3
    const int rbase = warp * 32;      // CTA-local row base for this warp

    // row pointers: rq[T] = item row (16T+q), rq8[T] = item row (16T+q+8)
    const float* rq[2];
    const float* rq8[2];
#pragma unroll
    for (int T = 0; T < 2; T++) {
        rq[T]  = xs + (rbase + 16 * T + q) * OBS;
        rq8[T] = rq[T] + 8 * OBS;
    }

    // ================= self encoder: 4 -> 32 -> 16 =================
    u64 spv[2][2][2];
    {
        EncW E;
        load_encw<4>(E, sw->en_w1, sw->en_b1, sw->en_w2, sw->en_b2, q, t);
#pragma unroll
        for (int T = 0; T < 2; T++) {
            uint32_t a0 = tf32a(rq[T][t]);
            uint32_t a1 = tf32a(rq8[T][t]);
            u64 epT[2][2];
            enc_mma(a0, a1, 0u, 0u, E, epT);
            spv[T][0][0] = epT[0][0]; spv[T][0][1] = epT[0][1];
            spv[T][1][0] = epT[1][0]; spv[T][1][1] = epT[1][1];
        }
    }

    u64 ov[2][2][2], fv[2][2][2];

    // ================= other-agent attention: 15 entities, K=5 =================
    {
        EncW E;
        load_encw<5>(E, sw->oa_w1, sw->oa_b1, sw->oa_w2, sw->oa_b2, q, t);
        // lane-specific k=t offset within row: t0:4, t1:5, t2:34, t3:35 (+2i)
        const int off0 = 4 + (t & 1) + 30 * (t >> 1);

        float mm[2][2], ll[2][2];
        u64 at[2][2][2];
#pragma unroll
        for (int T = 0; T < 2; T++)
#pragma unroll
            for (int b = 0; b < 2; b++) {
                mm[T][b] = -__int_as_float(0x7f800000);
                ll[T][b] = 0.f;
                at[T][0][b] = 0ull; at[T][1][b] = 0ull;
            }

#pragma unroll 1
        for (int i = 0; i < 15; i++) {
#pragma unroll
            for (int T = 0; T < 2; T++) {
                uint32_t a0 = tf32a(rq[T][off0 + 2 * i]);
                uint32_t a1 = tf32a(rq8[T][off0 + 2 * i]);
                uint32_t a2 = (t == 0) ? tf32a(rq[T][64 + i])  : 0u;
                uint32_t a3 = (t == 0) ? tf32a(rq8[T][64 + i]) : 0u;
                u64 ep[2][2];
                enc_mma(a0, a1, a2, a3, E, ep);

#pragma unroll
                for (int b = 0; b < 2; b++) {
                    u64 d = f2mul(spv[T][0][b], ep[0][b]);
                    d = f2fma(spv[T][1][b], ep[1][b], d);
                    float lo, hi; f2unpack(d, lo, hi);
                    float p = lo + hi;
                    p += sf1(p); p += sf2(p);
                    float s = p * 0.25f;
                    float nm = fmaxf(mm[T][b], s);
                    float corr = __expf(mm[T][b] - nm);
                    float pw   = __expf(s - nm);
                    mm[T][b] = nm;
                    ll[T][b] = ll[T][b] * corr + pw;
                    u64 cs = f2splat(corr), ps = f2splat(pw);
                    at[T][0][b] = f2fma(cs, at[T][0][b], f2mul(ps, ep[0][b]));
                    at[T][1][b] = f2fma(cs, at[T][1][b], f2mul(ps, ep[1][b]));
                }
            }
        }

        float g4[4], bt4[4];
        g4[0] = sw->oa_g[2 * t];     g4[1] = sw->oa_g[2 * t + 1];
        g4[2] = sw->oa_g[8 + 2 * t]; g4[3] = sw->oa_g[8 + 2 * t + 1];
        bt4[0] = sw->oa_bln[2 * t];     bt4[1] = sw->oa_bln[2 * t + 1];
        bt4[2] = sw->oa_bln[8 + 2 * t]; bt4[3] = sw->oa_bln[8 + 2 * t + 1];
#pragma unroll
        for (int T = 0; T < 2; T++)
#pragma unroll
            for (int b = 0; b < 2; b++) {
                float inv = __fdividef(1.f, ll[T][b]);
                float v0, v1, v2, v3;
                f2unpack(at[T][0][b], v0, v1);
                f2unpack(at[T][1][b], v2, v3);
                v0 *= inv; v1 *= inv; v2 *= inv; v3 *= inv;
                float sm = v0 + v1 + v2 + v3;
                sm += sf1(sm); sm += sf2(sm);
                float mu = sm * (1.f / 16.f);
                float c0 = v0 - mu, c1 = v1 - mu, c2 = v2 - mu, c3 = v3 - mu;
                float vr = c0 * c0 + c1 * c1 + c2 * c2 + c3 * c3;
                vr += sf1(vr); vr += sf2(vr);
                float rs = rsqrtf(vr * (1.f / 16.f) + 1e-5f);
                ov[T][0][b] = f2pack(fmaxf(c0 * rs * g4[0] + bt4[0], 0.f),
                                     fmaxf(c1 * rs * g4[1] + bt4[1], 0.f));
                ov[T][1][b] = f2pack(fmaxf(c2 * rs * g4[2] + bt4[2], 0.f),
                                     fmaxf(c3 * rs * g4[3] + bt4[3], 0.f));
            }
    }

    // ================= food attention: 16 entities, K=3 =================
    {
        EncW E;
        load_encw<3>(E, sw->g_w1, sw->g_b1, sw->g_w2, sw->g_b2, q, t);

        float mm[2][2], ll[2][2];
        u64 at[2][2][2];
#pragma unroll
        for (int T = 0; T < 2; T++)
#pragma unroll
            for (int b = 0; b < 2; b++) {
                mm[T][b] = -__int_as_float(0x7f800000);
                ll[T][b] = 0.f;
                at[T][0][b] = 0ull; at[T][1][b] = 0ull;
            }

#pragma unroll 1
        for (int i = 0; i < 16; i++) {
#pragma unroll
            for (int T = 0; T < 2; T++) {
                uint32_t a0 = (t < 3) ? tf32a(rq[T][79 + 3 * i + t])  : 0u;
                uint32_t a1 = (t < 3) ? tf32a(rq8[T][79 + 3 * i + t]) : 0u;
                u64 ep[2][2];
                enc_mma(a0, a1, 0u, 0u, E, ep);

#pragma unroll
                for (int b = 0; b < 2; b++) {
                    u64 d = f2mul(spv[T][0][b], ep[0][b]);
                    d = f2fma(spv[T][1][b], ep[1][b], d);
                    float lo, hi; f2unpack(d, lo, hi);
                    float p = lo + hi;
                    p += sf1(p); p += sf2(p);
                    float s = p * 0.25f;
                    float nm = fmaxf(mm[T][b], s);
                    float corr = __expf(mm[T][b] - nm);
                    float pw   = __expf(s - nm);
                    mm[T][b] = nm;
                    ll[T][b] = ll[T][b] * corr + pw;
                    u64 cs = f2splat(corr), ps = f2splat(pw);
                    at[T][0][b] = f2fma(cs, at[T][0][b], f2mul(ps, ep[0][b]));
                    at[T][1][b] = f2fma(cs, at[T][1][b], f2mul(ps, ep[1][b]));
                }
            }
        }

        float g4[4], bt4[4];
        g4[0] = sw->g_g[2 * t];     g4[1] = sw->g_g[2 * t + 1];
        g4[2] = sw->g_g[8 + 2 * t]; g4[3] = sw->g_g[8 + 2 * t + 1];
        bt4[0] = sw->g_bln[2 * t];     bt4[1] = sw->g_bln[2 * t + 1];
        bt4[2] = sw->g_bln[8 + 2 * t]; bt4[3] = sw->g_bln[8 + 2 * t + 1];
#pragma unroll
        for (int T = 0; T < 2; T++)
#pragma unroll
            for (int b = 0; b < 2; b++) {
                float inv = __fdividef(1.f, ll[T][b]);
                float v0, v1, v2, v3;
                f2unpack(at[T][0][b], v0, v1);
                f2unpack(at[T][1][b], v2, v3);
                v0 *= inv; v1 *= inv; v2 *= inv; v3 *= inv;
                float sm = v0 + v1 + v2 + v3;
                sm += sf1(sm); sm += sf2(sm);
                float mu = sm * (1.f / 16.f);
                float c0 = v0 - mu, c1 = v1 - mu, c2 = v2 - mu, c3 = v3 - mu;
                float vr = c0 * c0 + c1 * c1 + c2 * c2 + c3 * c3;
                vr += sf1(vr); vr += sf2(vr);
                float rs = rsqrtf(vr * (1.f / 16.f) + 1e-5f);
                fv[T][0][b] = f2pack(fmaxf(c0 * rs * g4[0] + bt4[0], 0.f),
                                     fmaxf(c1 * rs * g4[1] + bt4[1], 0.f));
                fv[T][1][b] = f2pack(fmaxf(c2 * rs * g4[2] + bt4[2], 0.f),
                                     fmaxf(c3 * rs * g4[3] + bt4[3], 0.f));
            }
    }

    // ============== merged vector -> smem (reuse this warp's x rows) ==============
    // merged[48]: cols 0..15 self, 16..31 food, 32..47 other.
#pragma unroll
    for (int T = 0; T < 2; T++)
#pragma unroll
        for (int b = 0; b < 2; b++) {
            float* M = xs + (rbase + 16 * T + q + 8 * b) * OBS;
#pragma unroll
            for (int N = 0; N < 2; N++) {
                float a, c;
                f2unpack(spv[T][N][b], a, c);
                M[8 * N + 2 * t] = a; M[8 * N + 2 * t + 1] = c;
                f2unpack(fv[T][N][b], a, c);
                M[16 + 8 * N + 2 * t] = a; M[16 + 8 * N + 2 * t + 1] = c;
                f2unpack(ov[T][N][b], a, c);
                M[32 + 8 * N + 2 * t] = a; M[32 + 8 * N + 2 * t + 1] = c;
            }
        }
    __syncwarp();

    // ============== m1: 48 -> 32 via mma (K=48, 6 k-steps) ==============
    {
        uint32_t Am[2][6][4];
#pragma unroll
        for (int T = 0; T < 2; T++) {
#pragma unroll
            for (int s = 0; s < 6; s++) {
                Am[T][s][0] = tf32a(rq[T][8 * s + t]);
                Am[T][s][1] = tf32a(rq8[T][8 * s + t]);
                Am[T][s][2] = tf32a(rq[T][8 * s + t + 4]);
                Am[T][s][3] = tf32a(rq8[T][8 * s + t + 4]);
            }
        }
#pragma unroll
        for (int N = 0; N < 4; N++) {
            uint32_t Bm[6][2];
#pragma unroll
            for (int s = 0; s < 6; s++) {
                Bm[s][0] = tf32w(sw->m_w1[(8 * s + t) * 32 + 8 * N + q]);
                Bm[s][1] = tf32w(sw->m_w1[(8 * s + t + 4) * 32 + 8 * N + q]);
            }
            float bb0 = sw->m_b1[8 * N + 2 * t], bb1 = sw->m_b1[8 * N + 2 * t + 1];
#pragma unroll
            for (int T = 0; T < 2; T++) {
                float c0 = bb0, c1 = bb1, c2 = bb0, c3 = bb1;
#pragma unroll
                for (int s = 0; s < 6; s++)
                    mma8(c0, c1, c2, c3,
                         Am[T][s][0], Am[T][s][1], Am[T][s][2], Am[T][s][3],
                         Bm[s][0], Bm[s][1]);
                float* r0w = xs + (rbase + 16 * T + q) * OBS;
                float* r1w = r0w + 8 * OBS;
                r0w[64 + 8 * N + 2 * t]     = lrelu(c0);
                r0w[64 + 8 * N + 2 * t + 1] = lrelu(c1);
                r1w[64 + 8 * N + 2 * t]     = lrelu(c2);
                r1w[64 + 8 * N + 2 * t + 1] = lrelu(c3);
            }
        }
    }
    __syncwarp();

    // ============== m2: 32 -> 32 via mma (K=32, 4 k-steps) ==============
    u64 h2p[2][4][2];
    {
        uint32_t Am[2][4][4];
#pragma unroll
        for (int T = 0; T < 2; T++) {
#pragma unroll
            for (int s = 0; s < 4; s++) {
                Am[T][s][0] = tf32a(rq[T][64 + 8 * s + t]);
                Am[T][s][1] = tf32a(rq8[T][64 + 8 * s + t]);
                Am[T][s][2] = tf32a(rq[T][64 + 8 * s + t + 4]);
                Am[T][s][3] = tf32a(rq8[T][64 + 8 * s + t + 4]);
            }
        }
#pragma unroll
        for (int N = 0; N < 4; N++) {
            uint32_t Bm[4][2];
#pragma unroll
            for (int s = 0; s < 4; s++) {
                Bm[s][0] = tf32w(sw->m_w2[(8 * s + t) * 32 + 8 * N + q]);
                Bm[s][1] = tf32w(sw->m_w2[(8 * s + t + 4) * 32 + 8 * N + q]);
            }
            float bb0 = sw->m_b2[8 * N + 2 * t], bb1 = sw->m_b2[8 * N + 2 * t + 1];
#pragma unroll
            for (int T = 0; T < 2; T++) {
                float c0 = bb0, c1 = bb1, c2 = bb0, c3 = bb1;
#pragma unroll
                for (int s = 0; s < 4; s++)
                    mma8(c0, c1, c2, c3,
                         Am[T][s][0], Am[T][s][1], Am[T][s][2], Am[T][s][3],
                         Bm[s][0], Bm[s][1]);
                h2p[T][N][0] = f2pack(lrelu(c0), lrelu(c1));
                h2p[T][N][1] = f2pack(lrelu(c2), lrelu(c3));
            }
        }
    }

    // ============== m3: 32 -> 2 (fp32, quad reduce) ==============
    {
        u64 w3p[4][2];
#pragma unroll
        for (int N = 0; N < 4; N++) {
            const int k = 8 * N + 2 * t;
            w3p[N][0] = *reinterpret_cast<const u64*>(sw->m_w3 + 2 * k);
            w3p[N][1] = *reinterpret_cast<const u64*>(sw->m_w3 + 2 * (k + 1));
        }
        const u64 bias = *reinterpret_cast<const u64*>(sw->m_b3);
#pragma unroll
        for (int T = 0; T < 2; T++)
#pragma unroll
            for (int b = 0; b < 2; b++) {
                u64 acc = 0ull;
#pragma unroll
                for (int N = 0; N < 4; N++) {
                    float ha, hb; f2unpack(h2p[T][N][b], ha, hb);
                    acc = f2fma(f2splat(ha), w3p[N][0], acc);
                    acc = f2fma(f2splat(hb), w3p[N][1], acc);
                }
                acc = f2add(acc, sh1(acc));
                acc = f2add(acc, sh2(acc));
                if (t == 0) {
                    acc = f2add(acc, bias);
                    float a, c; f2unpack(acc, a, c);
                    const int row = blockIdx.x * ROWS + rbase + 16 * T + q + 8 * b;
                    if (row < B)
                        reinterpret_cast<float2*>(out)[row] =
                            make_float2(tanhf(a), tanhf(c));
                }
            }
    }
}

extern "C" void kernel_launch(void* const* d_in, const int* in_sizes, int n_in,
                              void* d_out, int out_size) {
    const float* s_in = (const float*)d_in[0];
    const int B = in_sizes[0] / OBS;
    const size_t shbytes = (size_t)ROWS * OBS * sizeof(float) + sizeof(SW);
    cudaFuncSetAttribute(actor_kernel,
                         cudaFuncAttributeMaxDynamicSharedMemorySize, (int)shbytes);
    dim3 grid((B + ROWS - 1) / ROWS), block(NT);
    actor_kernel<<<grid, block, shbytes>>>(
        s_in,
        (const float*)d_in[1],  (const float*)d_in[2],
        (const float*)d_in[3],  (const float*)d_in[4],
        (const float*)d_in[5],  (const float*)d_in[6],
        (const float*)d_in[7],  (const float*)d_in[8],
        (const float*)d_in[9],  (const float*)d_in[10],
        (const float*)d_in[11], (const float*)d_in[12],
        (const float*)d_in[13], (const float*)d_in[14],
        (const float*)d_in[15], (const float*)d_in[16],
        (const float*)d_in[17], (const float*)d_in[18],
        (const float*)d_in[19], (const float*)d_in[20],
        (const float*)d_in[21], (const float*)d_in[22],
        (float*)d_out, B);
}